// round 14
// baseline (speedup 1.0000x reference)
#include <cuda_runtime.h>
#include <cuda_fp16.h>
#include <cstdint>

// ============================================================
// QuaternionLinear via 12-mult Cayley-Dickson/Gauss decomposition.
// R12: ONE CTA computes all 4 output components of its (m,n) block
// (B0 stream then B1 stream, 192 k-iters, BN=128, 64x32 warp tiles).
// Three fp16 SMEM snapshot buffers; single full-quad float4 epilogue
// (eliminates the R11 partial-quad write amplification).
//   A planes: q = [ar+ai, aj+ak, ai, ak, ar, aj]
//   B0 (comp0,1): [br|-bj|-(br+bi)|bj-bk|bi-br|bj+bk]
//   B1 (comp2,3): [bj|br|-(bj+bk)|bi-br|bk-bj|-(br+bi)]
// ============================================================

#define BATCH   4096
#define KTOT    6144          // per variant: 6 blocks x 1024
#define NOUT    1024

#define BM      128
#define BN      128
#define BK      64            // halves per K-tile (128B rows)
#define NKV     (KTOT / BK)   // 96 iters per variant
#define NKALL   (2 * NKV)     // 192 total
#define STAGES  3
#define NTHREADS 256

#define A_TILE_BYTES (BM * 128)   // 16384
#define B_TILE_BYTES (BN * 128)   // 16384
#define STAGE_BYTES  (A_TILE_BYTES + B_TILE_BYTES)   // 32768
#define PIPE_BYTES   (STAGES * STAGE_BYTES)          // 98304
#define SNAP_OFF     PIPE_BYTES
#define SNAP_BYTES   (BM * BN * 2)                   // 32768 per buffer
#define SMEM_TOTAL   (SNAP_OFF + 3 * SNAP_BYTES)     // 196608

// device-global scratch (allocation-free per harness rules)
__device__ __align__(128) __half g_A [(size_t)BATCH * KTOT];     // 50.3 MB
__device__ __align__(128) __half g_B0[(size_t)NOUT  * KTOT];     // 12.6 MB
__device__ __align__(128) __half g_B1[(size_t)NOUT  * KTOT];     // 12.6 MB

// ---------------- helpers ----------------
__device__ __forceinline__ uint32_t smem_u32(const void* p) {
    uint32_t a;
    asm("{ .reg .u64 t; cvta.to.shared.u64 t, %1; cvt.u32.u64 %0, t; }" : "=r"(a) : "l"(p));
    return a;
}
__device__ __forceinline__ void cp_async16(uint32_t dst, const void* src) {
    asm volatile("cp.async.cg.shared.global [%0], [%1], 16;\n" :: "r"(dst), "l"(src));
}
#define CP_COMMIT() asm volatile("cp.async.commit_group;\n" ::: "memory")
#define CP_WAIT(n)  asm volatile("cp.async.wait_group %0;\n" :: "n"(n) : "memory")

__device__ __forceinline__ void ldm_x4(uint32_t* r, uint32_t addr) {
    asm volatile("ldmatrix.sync.aligned.m8n8.x4.shared.b16 {%0,%1,%2,%3}, [%4];"
        : "=r"(r[0]), "=r"(r[1]), "=r"(r[2]), "=r"(r[3]) : "r"(addr));
}
__device__ __forceinline__ void mma16816(float* c, const uint32_t* a, const uint32_t* b) {
    asm volatile(
        "mma.sync.aligned.m16n8k16.row.col.f32.f16.f16.f32 "
        "{%0,%1,%2,%3}, {%4,%5,%6,%7}, {%8,%9}, {%0,%1,%2,%3};"
        : "+f"(c[0]), "+f"(c[1]), "+f"(c[2]), "+f"(c[3])
        : "r"(a[0]), "r"(a[1]), "r"(a[2]), "r"(a[3]), "r"(b[0]), "r"(b[1]));
}
__device__ __forceinline__ uint32_t sw128(uint32_t off) {
    return off ^ ((off >> 3) & 0x70);
}
__device__ __forceinline__ __half2 h2(float a, float b) { return __floats2half2_rn(a, b); }

// ---------------- Prep: A planes ----------------
__global__ void prep_a_kernel(const float4* __restrict__ x) {
    int t = blockIdx.x * blockDim.x + threadIdx.x;
    if (t >= BATCH * 512) return;
    int b  = t >> 9;
    int ip = (t & 511) << 1;
    const float4* xr = x + ((size_t)b * 1024 + ip);
    float4 v0 = xr[0], v1 = xr[1];
    __half* row = g_A + (size_t)b * KTOT;
    *reinterpret_cast<__half2*>(row +    0 + ip) = h2(v0.x + v0.y, v1.x + v1.y); // ar+ai
    *reinterpret_cast<__half2*>(row + 1024 + ip) = h2(v0.z + v0.w, v1.z + v1.w); // aj+ak
    *reinterpret_cast<__half2*>(row + 2048 + ip) = h2(v0.y, v1.y);               // ai
    *reinterpret_cast<__half2*>(row + 3072 + ip) = h2(v0.w, v1.w);               // ak
    *reinterpret_cast<__half2*>(row + 4096 + ip) = h2(v0.x, v1.x);               // ar
    *reinterpret_cast<__half2*>(row + 5120 + ip) = h2(v0.z, v1.z);               // aj
}

// ---------------- Prep: B planes (signs folded) ----------------
__global__ void prep_b_kernel(const float4* __restrict__ w) {
    int t = blockIdx.x * blockDim.x + threadIdx.x;
    if (t >= NOUT * 512) return;
    int o  = t >> 9;
    int ip = (t & 511) << 1;
    const float4* wr = w + ((size_t)o * 1024 + ip);
    float4 v0 = wr[0], v1 = wr[1];
    __half* r0 = g_B0 + (size_t)o * KTOT;
    __half* r1 = g_B1 + (size_t)o * KTOT;
    // variant 0: [ br | -bj | -(br+bi) | bj-bk | bi-br | bj+bk ]
    *reinterpret_cast<__half2*>(r0 +    0 + ip) = h2( v0.x,           v1.x);
    *reinterpret_cast<__half2*>(r0 + 1024 + ip) = h2(-v0.z,          -v1.z);
    *reinterpret_cast<__half2*>(r0 + 2048 + ip) = h2(-(v0.x + v0.y), -(v1.x + v1.y));
    *reinterpret_cast<__half2*>(r0 + 3072 + ip) = h2( v0.z - v0.w,    v1.z - v1.w);
    *reinterpret_cast<__half2*>(r0 + 4096 + ip) = h2( v0.y - v0.x,    v1.y - v1.x);
    *reinterpret_cast<__half2*>(r0 + 5120 + ip) = h2( v0.z + v0.w,    v1.z + v1.w);
    // variant 1: [ bj | br | -(bj+bk) | bi-br | bk-bj | -(br+bi) ]
    *reinterpret_cast<__half2*>(r1 +    0 + ip) = h2( v0.z,           v1.z);
    *reinterpret_cast<__half2*>(r1 + 1024 + ip) = h2( v0.x,           v1.x);
    *reinterpret_cast<__half2*>(r1 + 2048 + ip) = h2(-(v0.z + v0.w), -(v1.z + v1.w));
    *reinterpret_cast<__half2*>(r1 + 3072 + ip) = h2( v0.y - v0.x,    v1.y - v1.x);
    *reinterpret_cast<__half2*>(r1 + 4096 + ip) = h2( v0.w - v0.z,    v1.w - v1.z);
    *reinterpret_cast<__half2*>(r1 + 5120 + ip) = h2(-(v0.x + v0.y), -(v1.x + v1.y));
}

// ---------------- GEMM ----------------
__device__ __forceinline__ void load_stage(uint32_t sbase, int slot, int kt,
                                           int m0, int n0o, int tid) {
    uint32_t st = sbase + slot * STAGE_BYTES;
    int kv = (kt < NKV) ? kt : (kt - NKV);
    int k0 = kv * BK;
    const __half* Ap = g_A + (size_t)m0 * KTOT + k0;
    const __half* Bp = ((kt < NKV) ? g_B0 : g_B1) + (size_t)n0o * KTOT + k0;
#pragma unroll
    for (int c = 0; c < BM * 8; c += NTHREADS) {     // A: 1024 16B chunks
        int cc = c + tid;
        int row = cc >> 3, col = cc & 7;
        uint32_t sw = sw128((uint32_t)((row << 7) | (col << 4)));
        cp_async16(st + sw, Ap + (size_t)row * KTOT + (col << 3));
    }
#pragma unroll
    for (int c = 0; c < BN * 8; c += NTHREADS) {     // B: 1024 16B chunks
        int cc = c + tid;
        int row = cc >> 3, col = cc & 7;
        uint32_t sw = sw128((uint32_t)((row << 7) | (col << 4)));
        cp_async16(st + A_TILE_BYTES + sw, Bp + (size_t)row * KTOT + (col << 3));
    }
}

__global__ void __launch_bounds__(NTHREADS, 1) qgemm_kernel(const float* __restrict__ bias,
                                                            float* __restrict__ out) {
    extern __shared__ char smem[];
    uint32_t sbase = smem_u32(smem);
    int tid = threadIdx.x;
    int wid = tid >> 5;
    int lid = tid & 31;
    int m0  = blockIdx.y * BM;         // batch rows
    int n0o = blockIdx.x * BN;         // o columns

    // 3 snapshot buffers, per-thread private half2 slots
    __half2* SA = reinterpret_cast<__half2*>(smem + SNAP_OFF);
    __half2* SB = SA + SNAP_BYTES / 4;
    __half2* SC = SB + SNAP_BYTES / 4;

    int warp_m = wid & 1;   // 2 warps along M (64 rows each)
    int warp_n = wid >> 1;  // 4 warps along N (32 cols each)

    float acc[4][4][4];
#pragma unroll
    for (int i = 0; i < 4; ++i)
#pragma unroll
        for (int j = 0; j < 4; ++j)
#pragma unroll
            for (int v = 0; v < 4; ++v) acc[i][j][v] = 0.f;

    // Prologue: stages 0 .. STAGES-2
#pragma unroll
    for (int s = 0; s < STAGES - 1; ++s) {
        load_stage(sbase, s, s, m0, n0o, tid);
        CP_COMMIT();
    }

    // Per-lane ldmatrix address components (64x32 warp tile)
    int a_mat = lid >> 3;            // 0..3
    int a_r   = lid & 7;
    int a_row_base = warp_m * 64 + (a_mat & 1) * 8 + a_r;   // + mt*16
    int a_kb_base  = (a_mat >> 1) * 16;
    int b_row_base = warp_n * 32 + (a_mat >> 1) * 8 + a_r;  // + ntp*16
    int b_kb_base  = (a_mat & 1) * 16;

#define SNAP_STORE(S)                                                  \
    do {                                                               \
        _Pragma("unroll")                                              \
        for (int mt = 0; mt < 4; ++mt)                                 \
            _Pragma("unroll")                                          \
            for (int nt = 0; nt < 4; ++nt) {                           \
                int jb = (mt * 4 + nt) * 2;                            \
                (S)[(jb + 0) * NTHREADS + tid] = h2(acc[mt][nt][0], acc[mt][nt][1]); \
                (S)[(jb + 1) * NTHREADS + tid] = h2(acc[mt][nt][2], acc[mt][nt][3]); \
            }                                                          \
    } while (0)

#define SNAP_SWAP(S)                                                   \
    do {                                                               \
        _Pragma("unroll")                                              \
        for (int mt = 0; mt < 4; ++mt)                                 \
            _Pragma("unroll")                                          \
            for (int nt = 0; nt < 4; ++nt) {                           \
                int jb = (mt * 4 + nt) * 2;                            \
                __half2 o0 = (S)[(jb + 0) * NTHREADS + tid];           \
                __half2 o1 = (S)[(jb + 1) * NTHREADS + tid];           \
                (S)[(jb + 0) * NTHREADS + tid] = h2(acc[mt][nt][0], acc[mt][nt][1]); \
                (S)[(jb + 1) * NTHREADS + tid] = h2(acc[mt][nt][2], acc[mt][nt][3]); \
                float2 f0 = __half22float2(o0);                        \
                float2 f1 = __half22float2(o1);                        \
                acc[mt][nt][0] = f0.x; acc[mt][nt][1] = f0.y;          \
                acc[mt][nt][2] = f1.x; acc[mt][nt][3] = f1.y;          \
            }                                                          \
    } while (0)

    // Main loop: 192 iters, boundary actions between phases.
    //  P1(0-31)->shared0; SA<-; P2->comp0; swap SA; P3->comp1; SB<-,acc=0;
    //  P4(96-127)->shared1; SC<-; P5->comp2; swap SC; P6->comp3 (in acc).
    for (int k = 0; k < NKALL; ++k) {
        if (k == 32)       SNAP_STORE(SA);
        else if (k == 64)  SNAP_SWAP(SA);
        else if (k == 96) {
            SNAP_STORE(SB);
#pragma unroll
            for (int i = 0; i < 4; ++i)
#pragma unroll
                for (int j = 0; j < 4; ++j)
#pragma unroll
                    for (int v = 0; v < 4; ++v) acc[i][j][v] = 0.f;
        }
        else if (k == 128) SNAP_STORE(SC);
        else if (k == 160) SNAP_SWAP(SC);

        CP_WAIT(STAGES - 2);
        __syncthreads();
        int kload = k + STAGES - 1;
        if (kload < NKALL) load_stage(sbase, kload % STAGES, kload, m0, n0o, tid);
        CP_COMMIT();

        uint32_t a_base = sbase + (k % STAGES) * STAGE_BYTES;
        uint32_t b_base = a_base + A_TILE_BYTES;
#pragma unroll
        for (int ks = 0; ks < BK / 16; ++ks) {
            int kb = ks * 32;
            uint32_t af[4][4];
#pragma unroll
            for (int mt = 0; mt < 4; ++mt) {
                uint32_t off = (uint32_t)((a_row_base + mt * 16) << 7) + kb + a_kb_base;
                ldm_x4(af[mt], a_base + sw128(off));
            }
            uint32_t bf[8];
#pragma unroll
            for (int ntp = 0; ntp < 2; ++ntp) {
                uint32_t off = (uint32_t)((b_row_base + ntp * 16) << 7) + kb + b_kb_base;
                ldm_x4(&bf[ntp * 4], b_base + sw128(off));
            }
#pragma unroll
            for (int mt = 0; mt < 4; ++mt)
#pragma unroll
                for (int nt = 0; nt < 4; ++nt)
                    mma16816(acc[mt][nt], af[mt], &bf[nt * 2]);
        }
    }

    // Epilogue: full float4 quads {SA,SB,SC,acc} + bias quad, 128B-coalesced.
    int qrow = lid >> 2;        // 0..7
    int qcol = (lid & 3) * 2;   // 0,2,4,6
#pragma unroll
    for (int nt = 0; nt < 4; ++nt) {
        int o = n0o + warp_n * 32 + nt * 8 + qcol;   // o, o+1
        float4 b0 = __ldg(reinterpret_cast<const float4*>(bias) + o);
        float4 b1 = __ldg(reinterpret_cast<const float4*>(bias) + o + 1);
#pragma unroll
        for (int mt = 0; mt < 4; ++mt) {
            int gm = m0 + warp_m * 64 + mt * 16 + qrow;
            int jb = (mt * 4 + nt) * 2;
            float2 a0 = __half22float2(SA[(jb + 0) * NTHREADS + tid]); // comp0 rows qrow
            float2 a1 = __half22float2(SA[(jb + 1) * NTHREADS + tid]); // comp0 rows qrow+8
            float2 c0 = __half22float2(SB[(jb + 0) * NTHREADS + tid]); // comp1
            float2 c1 = __half22float2(SB[(jb + 1) * NTHREADS + tid]);
            float2 d0 = __half22float2(SC[(jb + 0) * NTHREADS + tid]); // comp2
            float2 d1 = __half22float2(SC[(jb + 1) * NTHREADS + tid]);
            float4 q;
            q.x = a0.x + b0.x; q.y = c0.x + b0.y; q.z = d0.x + b0.z; q.w = acc[mt][nt][0] + b0.w;
            *reinterpret_cast<float4*>(out + (size_t)gm * 4096 + (size_t)o * 4) = q;
            q.x = a0.y + b1.x; q.y = c0.y + b1.y; q.z = d0.y + b1.z; q.w = acc[mt][nt][1] + b1.w;
            *reinterpret_cast<float4*>(out + (size_t)gm * 4096 + (size_t)(o + 1) * 4) = q;
            q.x = a1.x + b0.x; q.y = c1.x + b0.y; q.z = d1.x + b0.z; q.w = acc[mt][nt][2] + b0.w;
            *reinterpret_cast<float4*>(out + (size_t)(gm + 8) * 4096 + (size_t)o * 4) = q;
            q.x = a1.y + b1.x; q.y = c1.y + b1.y; q.z = d1.y + b1.z; q.w = acc[mt][nt][3] + b1.w;
            *reinterpret_cast<float4*>(out + (size_t)(gm + 8) * 4096 + (size_t)(o + 1) * 4) = q;
        }
    }
}

// ---------------- launch ----------------
extern "C" void kernel_launch(void* const* d_in, const int* in_sizes, int n_in,
                              void* d_out, int out_size) {
    const float* x    = (const float*)d_in[0];
    const float* w    = (const float*)d_in[1];
    const float* bias = (const float*)d_in[2];
    float* out = (float*)d_out;

    prep_a_kernel<<<(BATCH * 512 + 255) / 256, 256>>>((const float4*)x);
    prep_b_kernel<<<(NOUT * 512 + 255) / 256, 256>>>((const float4*)w);

    cudaFuncSetAttribute(qgemm_kernel, cudaFuncAttributeMaxDynamicSharedMemorySize, SMEM_TOTAL);
    dim3 grid(NOUT / BN, BATCH / BM);   // (8, 32) = 256 CTAs
    qgemm_kernel<<<grid, NTHREADS, SMEM_TOTAL>>>(bias, out);
}

// round 15
// speedup vs baseline: 1.6569x; 1.6569x over previous
#include <cuda_runtime.h>
#include <cuda_fp16.h>
#include <cstdint>

// ============================================================
// QuaternionLinear via 12-mult Cayley-Dickson/Gauss decomposition.
// R14 = R11 champion GEMM (BN=256, 64x64 warp tiles, 3-stage,
// smem fp16 snapshot + swap, 2 variant CTAs) with the two prep
// kernels fused into ONE launch via grid.z dispatch -> 2-launch
// pattern so ncu profiles qgemm.
//   variant0 (out_r,out_i): B0=[br|-bj|-(br+bi)|bj-bk|bi-br|bj+bk]
//   variant1 (out_j,out_k): B1=[bj|br|-(bj+bk)|bi-br|bk-bj|-(br+bi)]
//   A planes: q = [ar+ai, aj+ak, ai, ak, ar, aj]
// ============================================================

#define BATCH   4096
#define KTOT    6144
#define NOUT    1024

#define BM      128
#define BN      256
#define BK      64            // halves per K-tile (128B rows)
#define NK      (KTOT / BK)   // 96
#define STAGES  3
#define NTHREADS 256

#define A_TILE_BYTES (BM * 128)   // 16384
#define B_TILE_BYTES (BN * 128)   // 32768
#define STAGE_BYTES  (A_TILE_BYTES + B_TILE_BYTES)   // 49152
#define PIPE_BYTES   (STAGES * STAGE_BYTES)          // 147456
#define SNAP_OFF     PIPE_BYTES
#define SNAP_BYTES   (BM * BN * 2)                   // 65536 (fp16)
#define SMEM_TOTAL   (SNAP_OFF + SNAP_BYTES)         // 212992

// device-global scratch (allocation-free per harness rules)
__device__ __align__(128) __half g_A [(size_t)BATCH * KTOT];     // 50.3 MB
__device__ __align__(128) __half g_B0[(size_t)NOUT  * KTOT];     // 12.6 MB
__device__ __align__(128) __half g_B1[(size_t)NOUT  * KTOT];     // 12.6 MB

// ---------------- helpers ----------------
__device__ __forceinline__ uint32_t smem_u32(const void* p) {
    uint32_t a;
    asm("{ .reg .u64 t; cvta.to.shared.u64 t, %1; cvt.u32.u64 %0, t; }" : "=r"(a) : "l"(p));
    return a;
}
__device__ __forceinline__ void cp_async16(uint32_t dst, const void* src) {
    asm volatile("cp.async.cg.shared.global [%0], [%1], 16;\n" :: "r"(dst), "l"(src));
}
#define CP_COMMIT() asm volatile("cp.async.commit_group;\n" ::: "memory")
#define CP_WAIT(n)  asm volatile("cp.async.wait_group %0;\n" :: "n"(n) : "memory")

__device__ __forceinline__ void ldm_x4(uint32_t* r, uint32_t addr) {
    asm volatile("ldmatrix.sync.aligned.m8n8.x4.shared.b16 {%0,%1,%2,%3}, [%4];"
        : "=r"(r[0]), "=r"(r[1]), "=r"(r[2]), "=r"(r[3]) : "r"(addr));
}
__device__ __forceinline__ void mma16816(float* c, const uint32_t* a, const uint32_t* b) {
    asm volatile(
        "mma.sync.aligned.m16n8k16.row.col.f32.f16.f16.f32 "
        "{%0,%1,%2,%3}, {%4,%5,%6,%7}, {%8,%9}, {%0,%1,%2,%3};"
        : "+f"(c[0]), "+f"(c[1]), "+f"(c[2]), "+f"(c[3])
        : "r"(a[0]), "r"(a[1]), "r"(a[2]), "r"(a[3]), "r"(b[0]), "r"(b[1]));
}
__device__ __forceinline__ uint32_t sw128(uint32_t off) {
    return off ^ ((off >> 3) & 0x70);
}
__device__ __forceinline__ __half2 h2(float a, float b) { return __floats2half2_rn(a, b); }

// ---------------- Fused prep (grid.z dispatch, uniform per block) ----------
// z=0: blocks 0..4095, each thread handles 2 x-rows-of-pairs (BATCH*512 work)
// z=1: blocks with t < NOUT*512 build both B matrices; rest exit.
__global__ void prep_kernel(const float4* __restrict__ x, const float4* __restrict__ w) {
    if (blockIdx.z == 0) {
#pragma unroll
        for (int s = 0; s < 2; ++s) {
            int t = (int)blockIdx.x * 512 + s * 256 + (int)threadIdx.x;   // < BATCH*512
            int b  = t >> 9;
            int ip = (t & 511) << 1;
            const float4* xr = x + ((size_t)b * 1024 + ip);
            float4 v0 = xr[0], v1 = xr[1];
            __half* row = g_A + (size_t)b * KTOT;
            *reinterpret_cast<__half2*>(row +    0 + ip) = h2(v0.x + v0.y, v1.x + v1.y); // ar+ai
            *reinterpret_cast<__half2*>(row + 1024 + ip) = h2(v0.z + v0.w, v1.z + v1.w); // aj+ak
            *reinterpret_cast<__half2*>(row + 2048 + ip) = h2(v0.y, v1.y);               // ai
            *reinterpret_cast<__half2*>(row + 3072 + ip) = h2(v0.w, v1.w);               // ak
            *reinterpret_cast<__half2*>(row + 4096 + ip) = h2(v0.x, v1.x);               // ar
            *reinterpret_cast<__half2*>(row + 5120 + ip) = h2(v0.z, v1.z);               // aj
        }
    } else {
        int t = (int)blockIdx.x * 256 + (int)threadIdx.x;
        if (t >= NOUT * 512) return;
        int o  = t >> 9;
        int ip = (t & 511) << 1;
        const float4* wr = w + ((size_t)o * 1024 + ip);
        float4 v0 = wr[0], v1 = wr[1];
        __half* r0 = g_B0 + (size_t)o * KTOT;
        __half* r1 = g_B1 + (size_t)o * KTOT;
        // variant 0: [ br | -bj | -(br+bi) | bj-bk | bi-br | bj+bk ]
        *reinterpret_cast<__half2*>(r0 +    0 + ip) = h2( v0.x,           v1.x);
        *reinterpret_cast<__half2*>(r0 + 1024 + ip) = h2(-v0.z,          -v1.z);
        *reinterpret_cast<__half2*>(r0 + 2048 + ip) = h2(-(v0.x + v0.y), -(v1.x + v1.y));
        *reinterpret_cast<__half2*>(r0 + 3072 + ip) = h2( v0.z - v0.w,    v1.z - v1.w);
        *reinterpret_cast<__half2*>(r0 + 4096 + ip) = h2( v0.y - v0.x,    v1.y - v1.x);
        *reinterpret_cast<__half2*>(r0 + 5120 + ip) = h2( v0.z + v0.w,    v1.z + v1.w);
        // variant 1: [ bj | br | -(bj+bk) | bi-br | bk-bj | -(br+bi) ]
        *reinterpret_cast<__half2*>(r1 +    0 + ip) = h2( v0.z,           v1.z);
        *reinterpret_cast<__half2*>(r1 + 1024 + ip) = h2( v0.x,           v1.x);
        *reinterpret_cast<__half2*>(r1 + 2048 + ip) = h2(-(v0.z + v0.w), -(v1.z + v1.w));
        *reinterpret_cast<__half2*>(r1 + 3072 + ip) = h2( v0.y - v0.x,    v1.y - v1.x);
        *reinterpret_cast<__half2*>(r1 + 4096 + ip) = h2( v0.w - v0.z,    v1.w - v1.z);
        *reinterpret_cast<__half2*>(r1 + 5120 + ip) = h2(-(v0.x + v0.y), -(v1.x + v1.y));
    }
}

// ---------------- GEMM (identical to R11 champion) ----------------
__device__ __forceinline__ void load_stage(uint32_t sbase, int slot, int kt,
                                           int m0, int n0o, int tid,
                                           const __half* __restrict__ Bmat) {
    uint32_t st = sbase + slot * STAGE_BYTES;
    int k0 = kt * BK;
    const __half* Ap = g_A  + (size_t)m0  * KTOT + k0;
    const __half* Bp = Bmat + (size_t)n0o * KTOT + k0;
#pragma unroll
    for (int c = 0; c < BM * 8; c += NTHREADS) {     // A: 1024 16B chunks
        int cc = c + tid;
        int row = cc >> 3, col = cc & 7;
        uint32_t sw = sw128((uint32_t)((row << 7) | (col << 4)));
        cp_async16(st + sw, Ap + (size_t)row * KTOT + (col << 3));
    }
#pragma unroll
    for (int c = 0; c < BN * 8; c += NTHREADS) {     // B: 2048 16B chunks
        int cc = c + tid;
        int row = cc >> 3, col = cc & 7;
        uint32_t sw = sw128((uint32_t)((row << 7) | (col << 4)));
        cp_async16(st + A_TILE_BYTES + sw, Bp + (size_t)row * KTOT + (col << 3));
    }
}

#define KITER(kvar)                                                               \
    do {                                                                          \
        CP_WAIT(STAGES - 2);                                                      \
        __syncthreads();                                                          \
        int kload = (kvar) + STAGES - 1;                                          \
        if (kload < NK) load_stage(sbase, kload % STAGES, kload, m0, n0o, tid, Bmat); \
        CP_COMMIT();                                                              \
        uint32_t a_base = sbase + ((kvar) % STAGES) * STAGE_BYTES;                \
        uint32_t b_base = a_base + A_TILE_BYTES;                                  \
        _Pragma("unroll")                                                         \
        for (int ks = 0; ks < BK / 16; ++ks) {                                    \
            int kb = ks * 32;                                                     \
            uint32_t af[4][4];                                                    \
            _Pragma("unroll")                                                     \
            for (int mt = 0; mt < 4; ++mt) {                                      \
                uint32_t off = (uint32_t)((a_row_base + mt * 16) << 7) + kb + a_kb_base; \
                ldm_x4(af[mt], a_base + sw128(off));                              \
            }                                                                     \
            uint32_t bf[4][4];                                                    \
            _Pragma("unroll")                                                     \
            for (int ntp = 0; ntp < 4; ++ntp) {                                   \
                uint32_t off = (uint32_t)((b_row_base + ntp * 16) << 7) + kb + b_kb_base; \
                ldm_x4(bf[ntp], b_base + sw128(off));                             \
            }                                                                     \
            _Pragma("unroll")                                                     \
            for (int mt = 0; mt < 4; ++mt)                                        \
                _Pragma("unroll")                                                 \
                for (int nt = 0; nt < 8; ++nt)                                    \
                    mma16816(acc[mt][nt], af[mt], &bf[nt >> 1][(nt & 1) * 2]);    \
        }                                                                         \
    } while (0)

__global__ void __launch_bounds__(NTHREADS, 1) qgemm_kernel(const float* __restrict__ bias,
                                                            float* __restrict__ out) {
    extern __shared__ char smem[];
    uint32_t sbase = smem_u32(smem);
    int tid = threadIdx.x;
    int wid = tid >> 5;
    int lid = tid & 31;
    int m0  = blockIdx.y * BM;         // batch rows
    int n0o = blockIdx.x * BN;         // o columns
    const __half* Bmat = blockIdx.z ? g_B1 : g_B0;
    int zc = (int)blockIdx.z * 2;

    __half2* S = reinterpret_cast<__half2*>(smem + SNAP_OFF);  // per-thread slots

    int warp_m = wid & 1;   // 2 warps along M (64 rows each)
    int warp_n = wid >> 1;  // 4 warps along N (64 cols each)

    float acc[4][8][4];
#pragma unroll
    for (int i = 0; i < 4; ++i)
#pragma unroll
        for (int j = 0; j < 8; ++j)
#pragma unroll
            for (int v = 0; v < 4; ++v) acc[i][j][v] = 0.f;

    // Prologue: stages 0 .. STAGES-2
#pragma unroll
    for (int s = 0; s < STAGES - 1; ++s) {
        load_stage(sbase, s, s, m0, n0o, tid, Bmat);
        CP_COMMIT();
    }

    // Per-lane ldmatrix address components (64x64 warp tile geometry)
    int a_mat = lid >> 3;            // 0..3
    int a_r   = lid & 7;
    int a_row_base = warp_m * 64 + (a_mat & 1) * 8 + a_r;   // + mt*16
    int a_kb_base  = (a_mat >> 1) * 16;
    int b_row_base = warp_n * 64 + (a_mat >> 1) * 8 + a_r;  // + ntp*16
    int b_kb_base  = (a_mat & 1) * 16;

    // Phase 1: K-blocks 0..1 (shared Gauss term)
    for (int k = 0; k < 32; ++k) KITER(k);

    // Snapshot acc -> smem fp16 (per-thread private slots, conflict-free)
#pragma unroll
    for (int mt = 0; mt < 4; ++mt)
#pragma unroll
        for (int nt = 0; nt < 8; ++nt) {
            int jb = (mt * 8 + nt) * 2;
            S[(jb + 0) * NTHREADS + tid] = h2(acc[mt][nt][0], acc[mt][nt][1]);
            S[(jb + 1) * NTHREADS + tid] = h2(acc[mt][nt][2], acc[mt][nt][3]);
        }

    // Phase 2: K-blocks 2..3 (acc completes comp zc)
    for (int k = 32; k < 64; ++k) KITER(k);

    // Swap: snap <- comp-zc result; acc <- shared Gauss term
#pragma unroll
    for (int mt = 0; mt < 4; ++mt)
#pragma unroll
        for (int nt = 0; nt < 8; ++nt) {
            int jb = (mt * 8 + nt) * 2;
            __half2 o0 = S[(jb + 0) * NTHREADS + tid];
            __half2 o1 = S[(jb + 1) * NTHREADS + tid];
            S[(jb + 0) * NTHREADS + tid] = h2(acc[mt][nt][0], acc[mt][nt][1]);
            S[(jb + 1) * NTHREADS + tid] = h2(acc[mt][nt][2], acc[mt][nt][3]);
            float2 f0 = __half22float2(o0);
            float2 f1 = __half22float2(o1);
            acc[mt][nt][0] = f0.x; acc[mt][nt][1] = f0.y;
            acc[mt][nt][2] = f1.x; acc[mt][nt][3] = f1.y;
        }

    // Phase 3: K-blocks 4..5 (acc completes comp zc+1)
    for (int k = 64; k < NK; ++k) KITER(k);

    // Combined epilogue: comp zc from smem, comp zc+1 from acc -> float2 stores
    int qrow = lid >> 2;        // 0..7
    int qcol = (lid & 3) * 2;   // 0,2,4,6
#pragma unroll
    for (int nt = 0; nt < 8; ++nt) {
        int o = n0o + warp_n * 64 + nt * 8 + qcol;   // o, o+1
        float2 bo  = *reinterpret_cast<const float2*>(bias + o * 4 + zc);
        float2 bo1 = *reinterpret_cast<const float2*>(bias + (o + 1) * 4 + zc);
#pragma unroll
        for (int mt = 0; mt < 4; ++mt) {
            int gm = m0 + warp_m * 64 + mt * 16 + qrow;
            int jb = (mt * 8 + nt) * 2;
            float2 s0 = __half22float2(S[(jb + 0) * NTHREADS + tid]);
            float2 s1 = __half22float2(S[(jb + 1) * NTHREADS + tid]);
            float2 v;
            v.x = s0.x + bo.x;  v.y = acc[mt][nt][0] + bo.y;
            *reinterpret_cast<float2*>(out + (size_t)gm * 4096 + o * 4 + zc) = v;
            v.x = s0.y + bo1.x; v.y = acc[mt][nt][1] + bo1.y;
            *reinterpret_cast<float2*>(out + (size_t)gm * 4096 + (o + 1) * 4 + zc) = v;
            v.x = s1.x + bo.x;  v.y = acc[mt][nt][2] + bo.y;
            *reinterpret_cast<float2*>(out + (size_t)(gm + 8) * 4096 + o * 4 + zc) = v;
            v.x = s1.y + bo1.x; v.y = acc[mt][nt][3] + bo1.y;
            *reinterpret_cast<float2*>(out + (size_t)(gm + 8) * 4096 + (o + 1) * 4 + zc) = v;
        }
    }
}

// ---------------- launch ----------------
extern "C" void kernel_launch(void* const* d_in, const int* in_sizes, int n_in,
                              void* d_out, int out_size) {
    const float* x    = (const float*)d_in[0];
    const float* w    = (const float*)d_in[1];
    const float* bias = (const float*)d_in[2];
    float* out = (float*)d_out;

    // One fused prep launch (z=0: x planes over 4096 blocks x 2 iters;
    // z=1: W planes, first 2048 blocks active) -> 2-launch pattern.
    dim3 pgrid(4096, 1, 2);
    prep_kernel<<<pgrid, 256>>>((const float4*)x, (const float4*)w);

    cudaFuncSetAttribute(qgemm_kernel, cudaFuncAttributeMaxDynamicSharedMemorySize, SMEM_TOTAL);
    dim3 grid(NOUT / BN, BATCH / BM, 2);   // (4, 32, 2) = 256 CTAs
    qgemm_kernel<<<grid, NTHREADS, SMEM_TOTAL>>>(bias, out);
}

// round 16
// speedup vs baseline: 1.8409x; 1.1110x over previous
#include <cuda_runtime.h>
#include <cuda_fp16.h>
#include <cstdint>

// ============================================================
// QuaternionLinear via 12-mult Cayley-Dickson/Gauss decomposition.
// R15: 12-mult arithmetic at R2's best-measured geometry:
//   BM=128/BN=128, 8 warps of 64x32, acc=64 regs, 2 CTAs/SM
//   (2-stage cp.async pipeline 64KB + fp16 snapshot 32KB = 96KB).
//   variant0 (out_r,out_i): B0=[br|-bj|-(br+bi)|bj-bk|bi-br|bj+bk]
//   variant1 (out_j,out_k): B1=[bj|br|-(bj+bk)|bi-br|bk-bj|-(br+bi)]
//   A planes: q = [ar+ai, aj+ak, ai, ak, ar, aj]
// ============================================================

#define BATCH   4096
#define KTOT    6144
#define NOUT    1024

#define BM      128
#define BN      128
#define BK      64            // halves per K-tile (128B rows)
#define NK      (KTOT / BK)   // 96
#define STAGES  2
#define NTHREADS 256

#define A_TILE_BYTES (BM * 128)   // 16384
#define B_TILE_BYTES (BN * 128)   // 16384
#define STAGE_BYTES  (A_TILE_BYTES + B_TILE_BYTES)   // 32768
#define PIPE_BYTES   (STAGES * STAGE_BYTES)          // 65536
#define SNAP_OFF     PIPE_BYTES
#define SNAP_BYTES   (BM * BN * 2)                   // 32768 (fp16)
#define SMEM_TOTAL   (SNAP_OFF + SNAP_BYTES)         // 98304 -> 2 CTAs/SM

// device-global scratch (allocation-free per harness rules)
__device__ __align__(128) __half g_A [(size_t)BATCH * KTOT];     // 50.3 MB
__device__ __align__(128) __half g_B0[(size_t)NOUT  * KTOT];     // 12.6 MB
__device__ __align__(128) __half g_B1[(size_t)NOUT  * KTOT];     // 12.6 MB

// ---------------- helpers ----------------
__device__ __forceinline__ uint32_t smem_u32(const void* p) {
    uint32_t a;
    asm("{ .reg .u64 t; cvta.to.shared.u64 t, %1; cvt.u32.u64 %0, t; }" : "=r"(a) : "l"(p));
    return a;
}
__device__ __forceinline__ void cp_async16(uint32_t dst, const void* src) {
    asm volatile("cp.async.cg.shared.global [%0], [%1], 16;\n" :: "r"(dst), "l"(src));
}
#define CP_COMMIT() asm volatile("cp.async.commit_group;\n" ::: "memory")
#define CP_WAIT(n)  asm volatile("cp.async.wait_group %0;\n" :: "n"(n) : "memory")

__device__ __forceinline__ void ldm_x4(uint32_t* r, uint32_t addr) {
    asm volatile("ldmatrix.sync.aligned.m8n8.x4.shared.b16 {%0,%1,%2,%3}, [%4];"
        : "=r"(r[0]), "=r"(r[1]), "=r"(r[2]), "=r"(r[3]) : "r"(addr));
}
__device__ __forceinline__ void mma16816(float* c, const uint32_t* a, const uint32_t* b) {
    asm volatile(
        "mma.sync.aligned.m16n8k16.row.col.f32.f16.f16.f32 "
        "{%0,%1,%2,%3}, {%4,%5,%6,%7}, {%8,%9}, {%0,%1,%2,%3};"
        : "+f"(c[0]), "+f"(c[1]), "+f"(c[2]), "+f"(c[3])
        : "r"(a[0]), "r"(a[1]), "r"(a[2]), "r"(a[3]), "r"(b[0]), "r"(b[1]));
}
__device__ __forceinline__ uint32_t sw128(uint32_t off) {
    return off ^ ((off >> 3) & 0x70);
}
__device__ __forceinline__ __half2 h2(float a, float b) { return __floats2half2_rn(a, b); }

// ---------------- Fused prep (grid.z dispatch; proven in R14) -------------
__global__ void prep_kernel(const float4* __restrict__ x, const float4* __restrict__ w) {
    if (blockIdx.z == 0) {
#pragma unroll
        for (int s = 0; s < 2; ++s) {
            int t = (int)blockIdx.x * 512 + s * 256 + (int)threadIdx.x;   // < BATCH*512
            int b  = t >> 9;
            int ip = (t & 511) << 1;
            const float4* xr = x + ((size_t)b * 1024 + ip);
            float4 v0 = xr[0], v1 = xr[1];
            __half* row = g_A + (size_t)b * KTOT;
            *reinterpret_cast<__half2*>(row +    0 + ip) = h2(v0.x + v0.y, v1.x + v1.y); // ar+ai
            *reinterpret_cast<__half2*>(row + 1024 + ip) = h2(v0.z + v0.w, v1.z + v1.w); // aj+ak
            *reinterpret_cast<__half2*>(row + 2048 + ip) = h2(v0.y, v1.y);               // ai
            *reinterpret_cast<__half2*>(row + 3072 + ip) = h2(v0.w, v1.w);               // ak
            *reinterpret_cast<__half2*>(row + 4096 + ip) = h2(v0.x, v1.x);               // ar
            *reinterpret_cast<__half2*>(row + 5120 + ip) = h2(v0.z, v1.z);               // aj
        }
    } else {
        int t = (int)blockIdx.x * 256 + (int)threadIdx.x;
        if (t >= NOUT * 512) return;
        int o  = t >> 9;
        int ip = (t & 511) << 1;
        const float4* wr = w + ((size_t)o * 1024 + ip);
        float4 v0 = wr[0], v1 = wr[1];
        __half* r0 = g_B0 + (size_t)o * KTOT;
        __half* r1 = g_B1 + (size_t)o * KTOT;
        // variant 0: [ br | -bj | -(br+bi) | bj-bk | bi-br | bj+bk ]
        *reinterpret_cast<__half2*>(r0 +    0 + ip) = h2( v0.x,           v1.x);
        *reinterpret_cast<__half2*>(r0 + 1024 + ip) = h2(-v0.z,          -v1.z);
        *reinterpret_cast<__half2*>(r0 + 2048 + ip) = h2(-(v0.x + v0.y), -(v1.x + v1.y));
        *reinterpret_cast<__half2*>(r0 + 3072 + ip) = h2( v0.z - v0.w,    v1.z - v1.w);
        *reinterpret_cast<__half2*>(r0 + 4096 + ip) = h2( v0.y - v0.x,    v1.y - v1.x);
        *reinterpret_cast<__half2*>(r0 + 5120 + ip) = h2( v0.z + v0.w,    v1.z + v1.w);
        // variant 1: [ bj | br | -(bj+bk) | bi-br | bk-bj | -(br+bi) ]
        *reinterpret_cast<__half2*>(r1 +    0 + ip) = h2( v0.z,           v1.z);
        *reinterpret_cast<__half2*>(r1 + 1024 + ip) = h2( v0.x,           v1.x);
        *reinterpret_cast<__half2*>(r1 + 2048 + ip) = h2(-(v0.z + v0.w), -(v1.z + v1.w));
        *reinterpret_cast<__half2*>(r1 + 3072 + ip) = h2( v0.y - v0.x,    v1.y - v1.x);
        *reinterpret_cast<__half2*>(r1 + 4096 + ip) = h2( v0.w - v0.z,    v1.w - v1.z);
        *reinterpret_cast<__half2*>(r1 + 5120 + ip) = h2(-(v0.x + v0.y), -(v1.x + v1.y));
    }
}

// ---------------- GEMM ----------------
__device__ __forceinline__ void load_stage(uint32_t sbase, int slot, int kt,
                                           int m0, int n0o, int tid,
                                           const __half* __restrict__ Bmat) {
    uint32_t st = sbase + slot * STAGE_BYTES;
    int k0 = kt * BK;
    const __half* Ap = g_A  + (size_t)m0  * KTOT + k0;
    const __half* Bp = Bmat + (size_t)n0o * KTOT + k0;
#pragma unroll
    for (int c = 0; c < BM * 8; c += NTHREADS) {     // A: 1024 16B chunks
        int cc = c + tid;
        int row = cc >> 3, col = cc & 7;
        uint32_t sw = sw128((uint32_t)((row << 7) | (col << 4)));
        cp_async16(st + sw, Ap + (size_t)row * KTOT + (col << 3));
    }
#pragma unroll
    for (int c = 0; c < BN * 8; c += NTHREADS) {     // B: 1024 16B chunks
        int cc = c + tid;
        int row = cc >> 3, col = cc & 7;
        uint32_t sw = sw128((uint32_t)((row << 7) | (col << 4)));
        cp_async16(st + A_TILE_BYTES + sw, Bp + (size_t)row * KTOT + (col << 3));
    }
}

// One k-iteration (2-stage: wait all, sync, prefetch k+1, compute k).
#define KITER(kvar)                                                               \
    do {                                                                          \
        CP_WAIT(0);                                                               \
        __syncthreads();                                                          \
        int kload = (kvar) + 1;                                                   \
        if (kload < NK) load_stage(sbase, kload & 1, kload, m0, n0o, tid, Bmat);  \
        CP_COMMIT();                                                              \
        uint32_t a_base = sbase + ((kvar) & 1) * STAGE_BYTES;                     \
        uint32_t b_base = a_base + A_TILE_BYTES;                                  \
        _Pragma("unroll")                                                         \
        for (int ks = 0; ks < BK / 16; ++ks) {                                    \
            int kb = ks * 32;                                                     \
            uint32_t af[4][4];                                                    \
            _Pragma("unroll")                                                     \
            for (int mt = 0; mt < 4; ++mt) {                                      \
                uint32_t off = (uint32_t)((a_row_base + mt * 16) << 7) + kb + a_kb_base; \
                ldm_x4(af[mt], a_base + sw128(off));                              \
            }                                                                     \
            uint32_t bf[8];                                                       \
            _Pragma("unroll")                                                     \
            for (int ntp = 0; ntp < 2; ++ntp) {                                   \
                uint32_t off = (uint32_t)((b_row_base + ntp * 16) << 7) + kb + b_kb_base; \
                ldm_x4(&bf[ntp * 4], b_base + sw128(off));                        \
            }                                                                     \
            _Pragma("unroll")                                                     \
            for (int mt = 0; mt < 4; ++mt)                                        \
                _Pragma("unroll")                                                 \
                for (int nt = 0; nt < 4; ++nt)                                    \
                    mma16816(acc[mt][nt], af[mt], &bf[nt * 2]);                   \
        }                                                                         \
    } while (0)

__global__ void __launch_bounds__(NTHREADS, 2) qgemm_kernel(const float* __restrict__ bias,
                                                            float* __restrict__ out) {
    extern __shared__ char smem[];
    uint32_t sbase = smem_u32(smem);
    int tid = threadIdx.x;
    int wid = tid >> 5;
    int lid = tid & 31;
    int m0  = blockIdx.y * BM;         // batch rows
    int n0o = blockIdx.x * BN;         // o columns
    const __half* Bmat = blockIdx.z ? g_B1 : g_B0;
    int zc = (int)blockIdx.z * 2;

    __half2* S = reinterpret_cast<__half2*>(smem + SNAP_OFF);  // per-thread slots

    int warp_m = wid & 1;   // 2 warps along M (64 rows each)
    int warp_n = wid >> 1;  // 4 warps along N (32 cols each)

    float acc[4][4][4];
#pragma unroll
    for (int i = 0; i < 4; ++i)
#pragma unroll
        for (int j = 0; j < 4; ++j)
#pragma unroll
            for (int v = 0; v < 4; ++v) acc[i][j][v] = 0.f;

    // Prologue: stage 0
    load_stage(sbase, 0, 0, m0, n0o, tid, Bmat);
    CP_COMMIT();

    // Per-lane ldmatrix address components (64x32 warp tile)
    int a_mat = lid >> 3;            // 0..3
    int a_r   = lid & 7;
    int a_row_base = warp_m * 64 + (a_mat & 1) * 8 + a_r;   // + mt*16
    int a_kb_base  = (a_mat >> 1) * 16;
    int b_row_base = warp_n * 32 + (a_mat >> 1) * 8 + a_r;  // + ntp*16
    int b_kb_base  = (a_mat & 1) * 16;

    // Phase 1: K-blocks 0..1 (shared Gauss term)
    for (int k = 0; k < 32; ++k) KITER(k);

    // Snapshot acc -> smem fp16 (per-thread private slots, conflict-free)
#pragma unroll
    for (int mt = 0; mt < 4; ++mt)
#pragma unroll
        for (int nt = 0; nt < 4; ++nt) {
            int jb = (mt * 4 + nt) * 2;
            S[(jb + 0) * NTHREADS + tid] = h2(acc[mt][nt][0], acc[mt][nt][1]);
            S[(jb + 1) * NTHREADS + tid] = h2(acc[mt][nt][2], acc[mt][nt][3]);
        }

    // Phase 2: K-blocks 2..3 (acc completes comp zc)
    for (int k = 32; k < 64; ++k) KITER(k);

    // Swap: snap <- comp-zc result; acc <- shared Gauss term
#pragma unroll
    for (int mt = 0; mt < 4; ++mt)
#pragma unroll
        for (int nt = 0; nt < 4; ++nt) {
            int jb = (mt * 4 + nt) * 2;
            __half2 o0 = S[(jb + 0) * NTHREADS + tid];
            __half2 o1 = S[(jb + 1) * NTHREADS + tid];
            S[(jb + 0) * NTHREADS + tid] = h2(acc[mt][nt][0], acc[mt][nt][1]);
            S[(jb + 1) * NTHREADS + tid] = h2(acc[mt][nt][2], acc[mt][nt][3]);
            float2 f0 = __half22float2(o0);
            float2 f1 = __half22float2(o1);
            acc[mt][nt][0] = f0.x; acc[mt][nt][1] = f0.y;
            acc[mt][nt][2] = f1.x; acc[mt][nt][3] = f1.y;
        }

    // Phase 3: K-blocks 4..5 (acc completes comp zc+1)
    for (int k = 64; k < NK; ++k) KITER(k);

    // Combined epilogue: comp zc from smem, comp zc+1 from acc -> float2 stores
    int qrow = lid >> 2;        // 0..7
    int qcol = (lid & 3) * 2;   // 0,2,4,6
#pragma unroll
    for (int nt = 0; nt < 4; ++nt) {
        int o = n0o + warp_n * 32 + nt * 8 + qcol;   // o, o+1
        float2 bo  = *reinterpret_cast<const float2*>(bias + o * 4 + zc);
        float2 bo1 = *reinterpret_cast<const float2*>(bias + (o + 1) * 4 + zc);
#pragma unroll
        for (int mt = 0; mt < 4; ++mt) {
            int gm = m0 + warp_m * 64 + mt * 16 + qrow;
            int jb = (mt * 4 + nt) * 2;
            float2 s0 = __half22float2(S[(jb + 0) * NTHREADS + tid]);
            float2 s1 = __half22float2(S[(jb + 1) * NTHREADS + tid]);
            float2 v;
            v.x = s0.x + bo.x;  v.y = acc[mt][nt][0] + bo.y;
            *reinterpret_cast<float2*>(out + (size_t)gm * 4096 + o * 4 + zc) = v;
            v.x = s0.y + bo1.x; v.y = acc[mt][nt][1] + bo1.y;
            *reinterpret_cast<float2*>(out + (size_t)gm * 4096 + (o + 1) * 4 + zc) = v;
            v.x = s1.x + bo.x;  v.y = acc[mt][nt][2] + bo.y;
            *reinterpret_cast<float2*>(out + (size_t)(gm + 8) * 4096 + o * 4 + zc) = v;
            v.x = s1.y + bo1.x; v.y = acc[mt][nt][3] + bo1.y;
            *reinterpret_cast<float2*>(out + (size_t)(gm + 8) * 4096 + (o + 1) * 4 + zc) = v;
        }
    }
}

// ---------------- launch ----------------
extern "C" void kernel_launch(void* const* d_in, const int* in_sizes, int n_in,
                              void* d_out, int out_size) {
    const float* x    = (const float*)d_in[0];
    const float* w    = (const float*)d_in[1];
    const float* bias = (const float*)d_in[2];
    float* out = (float*)d_out;

    dim3 pgrid(4096, 1, 2);
    prep_kernel<<<pgrid, 256>>>((const float4*)x, (const float4*)w);

    cudaFuncSetAttribute(qgemm_kernel, cudaFuncAttributeMaxDynamicSharedMemorySize, SMEM_TOTAL);
    dim3 grid(NOUT / BN, BATCH / BM, 2);   // (8, 32, 2) = 512 CTAs
    qgemm_kernel<<<grid, NTHREADS, SMEM_TOTAL>>>(bias, out);
}

// round 17
// speedup vs baseline: 1.9710x; 1.0706x over previous
#include <cuda_runtime.h>
#include <cuda_fp16.h>
#include <cstdint>

// ============================================================
// QuaternionLinear via 12-mult Cayley-Dickson/Gauss decomposition.
// R16: R15 skeleton (BM=BN=128, 2-stage cp.async, fp16 smem
// snapshot+swap, 2 CTAs/SM, 512 CTAs) but 4 warps of 64x64 per
// CTA (128 threads) -> LDSM-per-MMA 0.375 -> 0.25 to relieve the
// smem crossbar that pins tensor util at 59%.
//   variant0 (out_r,out_i): B0=[br|-bj|-(br+bi)|bj-bk|bi-br|bj+bk]
//   variant1 (out_j,out_k): B1=[bj|br|-(bj+bk)|bi-br|bk-bj|-(br+bi)]
//   A planes: q = [ar+ai, aj+ak, ai, ak, ar, aj]
// ============================================================

#define BATCH   4096
#define KTOT    6144
#define NOUT    1024

#define BM      128
#define BN      128
#define BK      64            // halves per K-tile (128B rows)
#define NK      (KTOT / BK)   // 96
#define STAGES  2
#define NTHREADS 128

#define A_TILE_BYTES (BM * 128)   // 16384
#define B_TILE_BYTES (BN * 128)   // 16384
#define STAGE_BYTES  (A_TILE_BYTES + B_TILE_BYTES)   // 32768
#define PIPE_BYTES   (STAGES * STAGE_BYTES)          // 65536
#define SNAP_OFF     PIPE_BYTES
#define SNAP_BYTES   (BM * BN * 2)                   // 32768 (fp16)
#define SMEM_TOTAL   (SNAP_OFF + SNAP_BYTES)         // 98304 -> 2 CTAs/SM

// device-global scratch (allocation-free per harness rules)
__device__ __align__(128) __half g_A [(size_t)BATCH * KTOT];     // 50.3 MB
__device__ __align__(128) __half g_B0[(size_t)NOUT  * KTOT];     // 12.6 MB
__device__ __align__(128) __half g_B1[(size_t)NOUT  * KTOT];     // 12.6 MB

// ---------------- helpers ----------------
__device__ __forceinline__ uint32_t smem_u32(const void* p) {
    uint32_t a;
    asm("{ .reg .u64 t; cvta.to.shared.u64 t, %1; cvt.u32.u64 %0, t; }" : "=r"(a) : "l"(p));
    return a;
}
__device__ __forceinline__ void cp_async16(uint32_t dst, const void* src) {
    asm volatile("cp.async.cg.shared.global [%0], [%1], 16;\n" :: "r"(dst), "l"(src));
}
#define CP_COMMIT() asm volatile("cp.async.commit_group;\n" ::: "memory")
#define CP_WAIT(n)  asm volatile("cp.async.wait_group %0;\n" :: "n"(n) : "memory")

__device__ __forceinline__ void ldm_x4(uint32_t* r, uint32_t addr) {
    asm volatile("ldmatrix.sync.aligned.m8n8.x4.shared.b16 {%0,%1,%2,%3}, [%4];"
        : "=r"(r[0]), "=r"(r[1]), "=r"(r[2]), "=r"(r[3]) : "r"(addr));
}
__device__ __forceinline__ void mma16816(float* c, const uint32_t* a, const uint32_t* b) {
    asm volatile(
        "mma.sync.aligned.m16n8k16.row.col.f32.f16.f16.f32 "
        "{%0,%1,%2,%3}, {%4,%5,%6,%7}, {%8,%9}, {%0,%1,%2,%3};"
        : "+f"(c[0]), "+f"(c[1]), "+f"(c[2]), "+f"(c[3])
        : "r"(a[0]), "r"(a[1]), "r"(a[2]), "r"(a[3]), "r"(b[0]), "r"(b[1]));
}
__device__ __forceinline__ uint32_t sw128(uint32_t off) {
    return off ^ ((off >> 3) & 0x70);
}
__device__ __forceinline__ __half2 h2(float a, float b) { return __floats2half2_rn(a, b); }

// ---------------- Fused prep (grid.z dispatch; proven) -------------
__global__ void prep_kernel(const float4* __restrict__ x, const float4* __restrict__ w) {
    if (blockIdx.z == 0) {
#pragma unroll
        for (int s = 0; s < 2; ++s) {
            int t = (int)blockIdx.x * 512 + s * 256 + (int)threadIdx.x;   // < BATCH*512
            int b  = t >> 9;
            int ip = (t & 511) << 1;
            const float4* xr = x + ((size_t)b * 1024 + ip);
            float4 v0 = xr[0], v1 = xr[1];
            __half* row = g_A + (size_t)b * KTOT;
            *reinterpret_cast<__half2*>(row +    0 + ip) = h2(v0.x + v0.y, v1.x + v1.y); // ar+ai
            *reinterpret_cast<__half2*>(row + 1024 + ip) = h2(v0.z + v0.w, v1.z + v1.w); // aj+ak
            *reinterpret_cast<__half2*>(row + 2048 + ip) = h2(v0.y, v1.y);               // ai
            *reinterpret_cast<__half2*>(row + 3072 + ip) = h2(v0.w, v1.w);               // ak
            *reinterpret_cast<__half2*>(row + 4096 + ip) = h2(v0.x, v1.x);               // ar
            *reinterpret_cast<__half2*>(row + 5120 + ip) = h2(v0.z, v1.z);               // aj
        }
    } else {
        int t = (int)blockIdx.x * 256 + (int)threadIdx.x;
        if (t >= NOUT * 512) return;
        int o  = t >> 9;
        int ip = (t & 511) << 1;
        const float4* wr = w + ((size_t)o * 1024 + ip);
        float4 v0 = wr[0], v1 = wr[1];
        __half* r0 = g_B0 + (size_t)o * KTOT;
        __half* r1 = g_B1 + (size_t)o * KTOT;
        // variant 0: [ br | -bj | -(br+bi) | bj-bk | bi-br | bj+bk ]
        *reinterpret_cast<__half2*>(r0 +    0 + ip) = h2( v0.x,           v1.x);
        *reinterpret_cast<__half2*>(r0 + 1024 + ip) = h2(-v0.z,          -v1.z);
        *reinterpret_cast<__half2*>(r0 + 2048 + ip) = h2(-(v0.x + v0.y), -(v1.x + v1.y));
        *reinterpret_cast<__half2*>(r0 + 3072 + ip) = h2( v0.z - v0.w,    v1.z - v1.w);
        *reinterpret_cast<__half2*>(r0 + 4096 + ip) = h2( v0.y - v0.x,    v1.y - v1.x);
        *reinterpret_cast<__half2*>(r0 + 5120 + ip) = h2( v0.z + v0.w,    v1.z + v1.w);
        // variant 1: [ bj | br | -(bj+bk) | bi-br | bk-bj | -(br+bi) ]
        *reinterpret_cast<__half2*>(r1 +    0 + ip) = h2( v0.z,           v1.z);
        *reinterpret_cast<__half2*>(r1 + 1024 + ip) = h2( v0.x,           v1.x);
        *reinterpret_cast<__half2*>(r1 + 2048 + ip) = h2(-(v0.z + v0.w), -(v1.z + v1.w));
        *reinterpret_cast<__half2*>(r1 + 3072 + ip) = h2( v0.y - v0.x,    v1.y - v1.x);
        *reinterpret_cast<__half2*>(r1 + 4096 + ip) = h2( v0.w - v0.z,    v1.w - v1.z);
        *reinterpret_cast<__half2*>(r1 + 5120 + ip) = h2(-(v0.x + v0.y), -(v1.x + v1.y));
    }
}

// ---------------- GEMM ----------------
__device__ __forceinline__ void load_stage(uint32_t sbase, int slot, int kt,
                                           int m0, int n0o, int tid,
                                           const __half* __restrict__ Bmat) {
    uint32_t st = sbase + slot * STAGE_BYTES;
    int k0 = kt * BK;
    const __half* Ap = g_A  + (size_t)m0  * KTOT + k0;
    const __half* Bp = Bmat + (size_t)n0o * KTOT + k0;
#pragma unroll
    for (int c = 0; c < BM * 8; c += NTHREADS) {     // A: 1024 chunks, 8/thread
        int cc = c + tid;
        int row = cc >> 3, col = cc & 7;
        uint32_t sw = sw128((uint32_t)((row << 7) | (col << 4)));
        cp_async16(st + sw, Ap + (size_t)row * KTOT + (col << 3));
    }
#pragma unroll
    for (int c = 0; c < BN * 8; c += NTHREADS) {     // B: 1024 chunks, 8/thread
        int cc = c + tid;
        int row = cc >> 3, col = cc & 7;
        uint32_t sw = sw128((uint32_t)((row << 7) | (col << 4)));
        cp_async16(st + A_TILE_BYTES + sw, Bp + (size_t)row * KTOT + (col << 3));
    }
}

// One k-iteration (2-stage: wait all, sync, prefetch k+1, compute k).
// 64x64 warp tile: per ks 8 ldm.x4 feed 32 mma.
#define KITER(kvar)                                                               \
    do {                                                                          \
        CP_WAIT(0);                                                               \
        __syncthreads();                                                          \
        int kload = (kvar) + 1;                                                   \
        if (kload < NK) load_stage(sbase, kload & 1, kload, m0, n0o, tid, Bmat);  \
        CP_COMMIT();                                                              \
        uint32_t a_base = sbase + ((kvar) & 1) * STAGE_BYTES;                     \
        uint32_t b_base = a_base + A_TILE_BYTES;                                  \
        _Pragma("unroll")                                                         \
        for (int ks = 0; ks < BK / 16; ++ks) {                                    \
            int kb = ks * 32;                                                     \
            uint32_t af[4][4];                                                    \
            _Pragma("unroll")                                                     \
            for (int mt = 0; mt < 4; ++mt) {                                      \
                uint32_t off = (uint32_t)((a_row_base + mt * 16) << 7) + kb + a_kb_base; \
                ldm_x4(af[mt], a_base + sw128(off));                              \
            }                                                                     \
            uint32_t bf[4][4];                                                    \
            _Pragma("unroll")                                                     \
            for (int ntp = 0; ntp < 4; ++ntp) {                                   \
                uint32_t off = (uint32_t)((b_row_base + ntp * 16) << 7) + kb + b_kb_base; \
                ldm_x4(bf[ntp], b_base + sw128(off));                             \
            }                                                                     \
            _Pragma("unroll")                                                     \
            for (int mt = 0; mt < 4; ++mt)                                        \
                _Pragma("unroll")                                                 \
                for (int nt = 0; nt < 8; ++nt)                                    \
                    mma16816(acc[mt][nt], af[mt], &bf[nt >> 1][(nt & 1) * 2]);    \
        }                                                                         \
    } while (0)

__global__ void __launch_bounds__(NTHREADS, 2) qgemm_kernel(const float* __restrict__ bias,
                                                            float* __restrict__ out) {
    extern __shared__ char smem[];
    uint32_t sbase = smem_u32(smem);
    int tid = threadIdx.x;
    int wid = tid >> 5;
    int lid = tid & 31;
    int m0  = blockIdx.y * BM;         // batch rows
    int n0o = blockIdx.x * BN;         // o columns
    const __half* Bmat = blockIdx.z ? g_B1 : g_B0;
    int zc = (int)blockIdx.z * 2;

    __half2* S = reinterpret_cast<__half2*>(smem + SNAP_OFF);  // per-thread slots

    int warp_m = wid & 1;   // 2 warps along M (64 rows each)
    int warp_n = wid >> 1;  // 2 warps along N (64 cols each)

    float acc[4][8][4];
#pragma unroll
    for (int i = 0; i < 4; ++i)
#pragma unroll
        for (int j = 0; j < 8; ++j)
#pragma unroll
            for (int v = 0; v < 4; ++v) acc[i][j][v] = 0.f;

    // Prologue: stage 0
    load_stage(sbase, 0, 0, m0, n0o, tid, Bmat);
    CP_COMMIT();

    // Per-lane ldmatrix address components (64x64 warp tile)
    int a_mat = lid >> 3;            // 0..3
    int a_r   = lid & 7;
    int a_row_base = warp_m * 64 + (a_mat & 1) * 8 + a_r;   // + mt*16
    int a_kb_base  = (a_mat >> 1) * 16;
    int b_row_base = warp_n * 64 + (a_mat >> 1) * 8 + a_r;  // + ntp*16
    int b_kb_base  = (a_mat & 1) * 16;

    // Phase 1: K-blocks 0..1 (shared Gauss term)
    for (int k = 0; k < 32; ++k) KITER(k);

    // Snapshot acc -> smem fp16 (per-thread private slots, conflict-free)
#pragma unroll
    for (int mt = 0; mt < 4; ++mt)
#pragma unroll
        for (int nt = 0; nt < 8; ++nt) {
            int jb = (mt * 8 + nt) * 2;
            S[(jb + 0) * NTHREADS + tid] = h2(acc[mt][nt][0], acc[mt][nt][1]);
            S[(jb + 1) * NTHREADS + tid] = h2(acc[mt][nt][2], acc[mt][nt][3]);
        }

    // Phase 2: K-blocks 2..3 (acc completes comp zc)
    for (int k = 32; k < 64; ++k) KITER(k);

    // Swap: snap <- comp-zc result; acc <- shared Gauss term
#pragma unroll
    for (int mt = 0; mt < 4; ++mt)
#pragma unroll
        for (int nt = 0; nt < 8; ++nt) {
            int jb = (mt * 8 + nt) * 2;
            __half2 o0 = S[(jb + 0) * NTHREADS + tid];
            __half2 o1 = S[(jb + 1) * NTHREADS + tid];
            S[(jb + 0) * NTHREADS + tid] = h2(acc[mt][nt][0], acc[mt][nt][1]);
            S[(jb + 1) * NTHREADS + tid] = h2(acc[mt][nt][2], acc[mt][nt][3]);
            float2 f0 = __half22float2(o0);
            float2 f1 = __half22float2(o1);
            acc[mt][nt][0] = f0.x; acc[mt][nt][1] = f0.y;
            acc[mt][nt][2] = f1.x; acc[mt][nt][3] = f1.y;
        }

    // Phase 3: K-blocks 4..5 (acc completes comp zc+1)
    for (int k = 64; k < NK; ++k) KITER(k);

    // Combined epilogue: comp zc from smem, comp zc+1 from acc -> float2 stores
    int qrow = lid >> 2;        // 0..7
    int qcol = (lid & 3) * 2;   // 0,2,4,6
#pragma unroll
    for (int nt = 0; nt < 8; ++nt) {
        int o = n0o + warp_n * 64 + nt * 8 + qcol;   // o, o+1
        float2 bo  = *reinterpret_cast<const float2*>(bias + o * 4 + zc);
        float2 bo1 = *reinterpret_cast<const float2*>(bias + (o + 1) * 4 + zc);
#pragma unroll
        for (int mt = 0; mt < 4; ++mt) {
            int gm = m0 + warp_m * 64 + mt * 16 + qrow;
            int jb = (mt * 8 + nt) * 2;
            float2 s0 = __half22float2(S[(jb + 0) * NTHREADS + tid]);
            float2 s1 = __half22float2(S[(jb + 1) * NTHREADS + tid]);
            float2 v;
            v.x = s0.x + bo.x;  v.y = acc[mt][nt][0] + bo.y;
            *reinterpret_cast<float2*>(out + (size_t)gm * 4096 + o * 4 + zc) = v;
            v.x = s0.y + bo1.x; v.y = acc[mt][nt][1] + bo1.y;
            *reinterpret_cast<float2*>(out + (size_t)gm * 4096 + (o + 1) * 4 + zc) = v;
            v.x = s1.x + bo.x;  v.y = acc[mt][nt][2] + bo.y;
            *reinterpret_cast<float2*>(out + (size_t)(gm + 8) * 4096 + o * 4 + zc) = v;
            v.x = s1.y + bo1.x; v.y = acc[mt][nt][3] + bo1.y;
            *reinterpret_cast<float2*>(out + (size_t)(gm + 8) * 4096 + (o + 1) * 4 + zc) = v;
        }
    }
}

// ---------------- launch ----------------
extern "C" void kernel_launch(void* const* d_in, const int* in_sizes, int n_in,
                              void* d_out, int out_size) {
    const float* x    = (const float*)d_in[0];
    const float* w    = (const float*)d_in[1];
    const float* bias = (const float*)d_in[2];
    float* out = (float*)d_out;

    dim3 pgrid(4096, 1, 2);
    prep_kernel<<<pgrid, 256>>>((const float4*)x, (const float4*)w);

    cudaFuncSetAttribute(qgemm_kernel, cudaFuncAttributeMaxDynamicSharedMemorySize, SMEM_TOTAL);
    dim3 grid(NOUT / BN, BATCH / BM, 2);   // (8, 32, 2) = 512 CTAs
    qgemm_kernel<<<grid, NTHREADS, SMEM_TOTAL>>>(bias, out);
}